// round 17
// baseline (speedup 1.0000x reference)
#include <cuda_runtime.h>
#include <cstdint>

// ---------------------------------------------------------------------------
// Router: r[b,e] = || W[e] @ x[b] ||_2
//   x: [8192,4096] f32, W: [16,64,4096] f32, out: [8192,16] f32
// GEMM C = X @ W^T via mma.sync.m16n8k16.bf16 (base sm_103 target).
// R17 vs R15 (219.6us = 31 prep + 188 GEMM): R13->R15 showed each lockstep
// __syncthreads costs ~1700cyc of convergence (warps drift; barrier resyncs
// the slowest every kt). R16 (occ-2) confirmed more concurrency never helps.
// -> replace BAR.SYNC with an mbarrier full/empty ring carrying ONE FULL
// ITERATION of slack: at iteration kt, produce stage kt+2 (wait: everyone
// done with kt-1, not kt), then consume stage kt. A warp blocks only if
// another warp is a whole iteration behind. BK=64, 3 stages (216KB),
// cp.async.mbarrier.arrive.noinc (no commit groups). Inner compute = R13's
// proven body; per-warp epilogue (no block sync). Prep unchanged.
// ---------------------------------------------------------------------------

#define BDIM   8192
#define DDIM   4096
#define EDIM   16
#define NTOT   1024
#define BM     128
#define BN     256
#define BK     64                      /* bf16 cols per stage = 128B/row    */
#define STAGES 3
#define KT     (DDIM / BK)             /* 64 mainloop iterations            */
#define RSB    192                     /* smem row stride (=64 mod 128:
                                          conflict-free 16B phases)          */
#define A_BYTES (BM * RSB)             /* 24576 */
#define B_BYTES (BN * RSB)             /* 49152 */
#define STG_BYTES (A_BYTES + B_BYTES)  /* 73728 */
#define SMEM_BYTES (STAGES * STG_BYTES)/* 221184 */

#define NX16 ((size_t)BDIM * DDIM / 16)
#define NW16 ((size_t)NTOT * DDIM / 16)

// bf16 scratch copies of the inputs (module-scope __device__ = legal scratch)
__device__ uint4 g_xb[(size_t)BDIM * DDIM / 8];   // 67 MB
__device__ uint4 g_wb[(size_t)NTOT * DDIM / 8];   //  8.4 MB

__device__ __forceinline__ void mma_bf16(float c[4],
                                         uint32_t a0, uint32_t a1,
                                         uint32_t a2, uint32_t a3,
                                         uint32_t b0, uint32_t b1) {
    asm volatile(
        "mma.sync.aligned.m16n8k16.row.col.f32.bf16.bf16.f32 "
        "{%0,%1,%2,%3}, {%4,%5,%6,%7}, {%8,%9}, {%0,%1,%2,%3};"
        : "+f"(c[0]), "+f"(c[1]), "+f"(c[2]), "+f"(c[3])
        : "r"(a0), "r"(a1), "r"(a2), "r"(a3), "r"(b0), "r"(b1));
}

__device__ __forceinline__ void cp16(uint32_t dst, const void* src) {
    asm volatile("cp.async.cg.shared.global [%0], [%1], 16;"
                 :: "r"(dst), "l"(src) : "memory");
}

__device__ __forceinline__ uint32_t pack_bf16x2(float lo, float hi) {
    uint32_t r;
    asm("cvt.rn.bf16x2.f32 %0, %1, %2;" : "=r"(r) : "f"(hi), "f"(lo));
    return r;
}

__device__ __forceinline__ void mbar_init(uint32_t a, uint32_t cnt) {
    asm volatile("mbarrier.init.shared.b64 [%0], %1;" :: "r"(a), "r"(cnt)
                 : "memory");
}
__device__ __forceinline__ void mbar_arrive(uint32_t a) {
    asm volatile("mbarrier.arrive.shared.b64 _, [%0];" :: "r"(a) : "memory");
}
__device__ __forceinline__ void cpasync_arrive(uint32_t a) {
    asm volatile("cp.async.mbarrier.arrive.noinc.shared.b64 [%0];"
                 :: "r"(a) : "memory");
}
__device__ __forceinline__ void mbar_wait(uint32_t a, uint32_t parity) {
    asm volatile(
        "{\n\t"
        ".reg .pred P1;\n\t"
        "WAIT_%=:\n\t"
        "mbarrier.try_wait.parity.shared.b64 P1, [%0], %1;\n\t"
        "@P1 bra.uni DONE_%=;\n\t"
        "bra.uni WAIT_%=;\n\t"
        "DONE_%=:\n\t"
        "}"
        :: "r"(a), "r"(parity) : "memory");
}

// ---------------------------------------------------------------------------
// Fused prep: f32 -> bf16 (RN, unbiased) for x and w in one launch.
// ---------------------------------------------------------------------------
__global__ void prep_xw(const float4* __restrict__ x,
                        const float4* __restrict__ w) {
    size_t i = (size_t)blockIdx.x * blockDim.x + threadIdx.x;
    const float4* src;
    uint4* dst;
    if (i < NX16) {
        src = x + 4 * i;              dst = g_xb + 2 * i;
    } else {
        size_t j = i - NX16;
        if (j >= NW16) return;
        src = w + 4 * j;              dst = g_wb + 2 * j;
    }
    float4 v0 = src[0], v1 = src[1], v2 = src[2], v3 = src[3];
    uint4 o0, o1;
    o0.x = pack_bf16x2(v0.x, v0.y);
    o0.y = pack_bf16x2(v0.z, v0.w);
    o0.z = pack_bf16x2(v1.x, v1.y);
    o0.w = pack_bf16x2(v1.z, v1.w);
    o1.x = pack_bf16x2(v2.x, v2.y);
    o1.y = pack_bf16x2(v2.z, v2.w);
    o1.z = pack_bf16x2(v3.x, v3.y);
    o1.w = pack_bf16x2(v3.z, v3.w);
    dst[0] = o0;
    dst[1] = o1;
}

// ---------------------------------------------------------------------------
// grid = (NTOT/BN = 4, BDIM/BM = 64), n fastest (A reused via L2).
// 8 warps: 2(m) x 4(n); warp tile 64x64 = one expert per warp.
// mbarrier ring: full[s]/empty[s] count=256. Iteration kt:
//   produce kt+2 into slot (kt+2)%3  [wait empty = all done with kt-1]
//   consume kt from slot kt%3        [wait full]
// ---------------------------------------------------------------------------
__global__ __launch_bounds__(256, 1)
void router_kernel(float* __restrict__ out) {
    extern __shared__ char smem[];
    __shared__ __align__(8) uint64_t mb_full[STAGES];
    __shared__ __align__(8) uint64_t mb_empty[STAGES];

    const int tid  = threadIdx.x;
    const int lane = tid & 31;
    const int wid  = tid >> 5;
    const int wm   = wid & 1;
    const int wn   = wid >> 1;

    const int m_base = blockIdx.y * BM;
    const int n_base = blockIdx.x * BN;

    uint32_t fullA[STAGES], emptyA[STAGES];
#pragma unroll
    for (int s = 0; s < STAGES; ++s) {
        fullA[s]  = (uint32_t)__cvta_generic_to_shared(&mb_full[s]);
        emptyA[s] = (uint32_t)__cvta_generic_to_shared(&mb_empty[s]);
    }
    if (tid == 0) {
#pragma unroll
        for (int s = 0; s < STAGES; ++s) {
            mbar_init(fullA[s], 256);
            mbar_init(emptyA[s], 256);
        }
    }
    __syncthreads();   // barriers visible before any cp.async arrive

    // ---- cp.async producer: thread -> (row = tid/8, 16B chunk = tid%8) ----
    const int lrow = tid >> 3;               // 0..31
    const int lch  = tid & 7;                // 0..7
    const char* gA = (const char*)g_xb
                   + ((size_t)(m_base + lrow) * DDIM + lch * 8) * 2;
    const char* gB = (const char*)g_wb
                   + ((size_t)(n_base + lrow) * DDIM + lch * 8) * 2;
    const uint32_t sbase = (uint32_t)__cvta_generic_to_shared(smem);
    const uint32_t sA0 = sbase + (uint32_t)(lrow * RSB + lch * 16);
    const uint32_t sB0 = sA0 + A_BYTES;

    auto load_stage = [&](int s, int kb /*bf16 col offset*/) {
        const uint32_t so = (uint32_t)(s * STG_BYTES);
        const char* ga = gA + (size_t)kb * 2;
#pragma unroll
        for (int p = 0; p < BM / 32; ++p)    // 4 passes of 32 rows
            cp16(sA0 + so + (uint32_t)(p * 32 * RSB),
                 ga + (size_t)(p * 32) * DDIM * 2);
        const char* gb = gB + (size_t)kb * 2;
#pragma unroll
        for (int p = 0; p < BN / 32; ++p)    // 8 passes of 32 rows
            cp16(sB0 + so + (uint32_t)(p * 32 * RSB),
                 gb + (size_t)(p * 32) * DDIM * 2);
    };

    // ---- prologue: fill kt = 0 (slot 0) and kt = 1 (slot 1) ---------------
    load_stage(0, 0);
    cpasync_arrive(fullA[0]);
    load_stage(1, BK);
    cpasync_arrive(fullA[1]);

    float acc[4][8][4];
#pragma unroll
    for (int mt = 0; mt < 4; ++mt)
#pragma unroll
        for (int nt = 0; nt < 8; ++nt)
#pragma unroll
            for (int i = 0; i < 4; ++i) acc[mt][nt][i] = 0.f;

    const int g = lane >> 2;                 // group (row) id
    const int q = lane & 3;                  // quad id
    const char* Aw = smem + (wm * 64 + g) * RSB + q * 16;
    const char* Bw = smem + A_BYTES + (wn * 64 + g) * RSB + q * 16;

#pragma unroll 1
    for (int kt = 0; kt < KT; ++kt) {
        // ---- produce stage kt+2 (slot = (kt+2)%3) --------------------------
        if (kt + 2 < KT) {
            const int pf   = kt + 2;
            const int slot = pf % 3;
            if (kt >= 1) mbar_wait(emptyA[slot], (uint32_t)(((kt - 1) / 3) & 1));
            load_stage(slot, pf * BK);
            cpasync_arrive(fullA[slot]);
        }

        // ---- consume stage kt ----------------------------------------------
        const int s = kt % 3;
        mbar_wait(fullA[s], (uint32_t)((kt / 3) & 1));

        const char* Ac = Aw + s * STG_BYTES;
        const char* Bc = Bw + s * STG_BYTES;

#pragma unroll
        for (int c2 = 0; c2 < 2; ++c2) {     // two 32-col chunks per stage
            const int co = c2 * 64;
            uint4 al[4], ah[4];              // A rows g, g+8 per mt
#pragma unroll
            for (int mt = 0; mt < 4; ++mt) {
                const char* p = Ac + mt * 16 * RSB + co;
                al[mt] = *reinterpret_cast<const uint4*>(p);
                ah[mt] = *reinterpret_cast<const uint4*>(p + 8 * RSB);
            }
            uint4 bv[8];
#pragma unroll
            for (int nt = 0; nt < 8; ++nt)
                bv[nt] = *reinterpret_cast<const uint4*>(Bc + nt * 8 * RSB + co);

            // instance 0: fragment halves .x/.y — 32 independent acc chains
#pragma unroll
            for (int mt = 0; mt < 4; ++mt)
#pragma unroll
                for (int nt = 0; nt < 8; ++nt)
                    mma_bf16(acc[mt][nt],
                             al[mt].x, ah[mt].x, al[mt].y, ah[mt].y,
                             bv[nt].x, bv[nt].y);
            // instance 1: fragment halves .z/.w
#pragma unroll
            for (int mt = 0; mt < 4; ++mt)
#pragma unroll
                for (int nt = 0; nt < 8; ++nt)
                    mma_bf16(acc[mt][nt],
                             al[mt].z, ah[mt].z, al[mt].w, ah[mt].w,
                             bv[nt].z, bv[nt].w);
        }

        mbar_arrive(emptyA[s]);              // done reading stage kt
    }

    // ---- epilogue: ||.||_2 over this warp's 64 n-cols (one expert) --------
    const int e = blockIdx.x * (BN / 64) + wn;
#pragma unroll
    for (int mt = 0; mt < 4; ++mt) {
        float s0 = 0.f, s1 = 0.f;
#pragma unroll
        for (int nt = 0; nt < 8; ++nt) {
            s0 = fmaf(acc[mt][nt][0], acc[mt][nt][0], s0);
            s0 = fmaf(acc[mt][nt][1], acc[mt][nt][1], s0);
            s1 = fmaf(acc[mt][nt][2], acc[mt][nt][2], s1);
            s1 = fmaf(acc[mt][nt][3], acc[mt][nt][3], s1);
        }
        s0 += __shfl_xor_sync(0xffffffffu, s0, 1);
        s0 += __shfl_xor_sync(0xffffffffu, s0, 2);
        s1 += __shfl_xor_sync(0xffffffffu, s1, 1);
        s1 += __shfl_xor_sync(0xffffffffu, s1, 2);
        if ((lane & 3) == 0) {
            const int row = m_base + wm * 64 + mt * 16 + g;
            out[(size_t)row * EDIM + e]       = sqrtf(s0);
            out[(size_t)(row + 8) * EDIM + e] = sqrtf(s1);
        }
    }
}

// ---------------------------------------------------------------------------
extern "C" void kernel_launch(void* const* d_in, const int* in_sizes, int n_in,
                              void* d_out, int out_size) {
    (void)in_sizes; (void)n_in; (void)out_size;
    const float* x = (const float*)d_in[0];   // [8192, 4096]
    const float* w = (const float*)d_in[1];   // [16, 64, 4096]
    float* out = (float*)d_out;               // [8192, 16]

    const size_t total = NX16 + NW16;
    prep_xw<<<(unsigned)((total + 255) / 256), 256>>>(
        (const float4*)x, (const float4*)w);

    cudaFuncSetAttribute(router_kernel,
                         cudaFuncAttributeMaxDynamicSharedMemorySize, SMEM_BYTES);
    router_kernel<<<dim3(NTOT / BN, BDIM / BM), 256, SMEM_BYTES>>>(out);
}